// round 1
// baseline (speedup 1.0000x reference)
#include <cuda_runtime.h>
#include <math.h>

// Problem: B=64, V=8, J=17, H=256
// keypoints_gt: (B,V,J,2) float32   -> d_in[0], 17408 elems
// heatmap:      (B,V,1,H,H) float32 -> d_in[1], 33554432 elems
// out: scalar float = mean over B*V*J of -log(hm[b,v, clip(ceil(ky)), clip(ceil(kx))])

#define NTOT   8704      // 64*8*17
#define JDIM   17
#define HDIM   256
#define NBLK   68        // 68 * 128 = 8704 exactly
#define NTHR   128

__device__ float g_partials[NBLK];

__global__ __launch_bounds__(NTHR) void heatmap_gather_kernel(
    const float* __restrict__ kp,   // (NTOT, 2)
    const float* __restrict__ hm)   // (B*V, H, H)
{
    const int i = blockIdx.x * NTHR + threadIdx.x;   // 0..8703, exact

    // coalesced float2 keypoint load
    const float2 k = reinterpret_cast<const float2*>(kp)[i];

    int xi = (int)ceilf(k.x);
    int yi = (int)ceilf(k.y);
    xi = min(max(xi, 0), HDIM - 1);
    yi = min(max(yi, 0), HDIM - 1);

    const int bv = i / JDIM;                         // (b*V + v)
    const long long off = (long long)bv * (HDIM * HDIM) + yi * HDIM + xi;

    const float val = __ldg(&hm[off]);
    float s = -__logf(val);   // vals in [0.001, 1] -> well-conditioned; fast log ok at 1e-3 tol

    // warp reduce
    #pragma unroll
    for (int o = 16; o > 0; o >>= 1)
        s += __shfl_down_sync(0xFFFFFFFFu, s, o);

    __shared__ float sm[NTHR / 32];
    const int lane = threadIdx.x & 31;
    const int wid  = threadIdx.x >> 5;
    if (lane == 0) sm[wid] = s;
    __syncthreads();

    if (wid == 0) {
        s = (lane < NTHR / 32) ? sm[lane] : 0.0f;
        #pragma unroll
        for (int o = 2; o > 0; o >>= 1)
            s += __shfl_down_sync(0xFFFFFFFFu, s, o);
        if (lane == 0) g_partials[blockIdx.x] = s;
    }
}

__global__ void final_reduce_kernel(float* __restrict__ out)
{
    const int lane = threadIdx.x;   // 32 threads
    float s = 0.0f;
    #pragma unroll
    for (int b = lane; b < NBLK; b += 32)
        s += g_partials[b];
    #pragma unroll
    for (int o = 16; o > 0; o >>= 1)
        s += __shfl_down_sync(0xFFFFFFFFu, s, o);
    if (lane == 0)
        out[0] = s * (1.0f / (float)NTOT);
}

extern "C" void kernel_launch(void* const* d_in, const int* in_sizes, int n_in,
                              void* d_out, int out_size)
{
    const float* kp = (const float*)d_in[0];
    const float* hm = (const float*)d_in[1];
    float* out = (float*)d_out;

    heatmap_gather_kernel<<<NBLK, NTHR>>>(kp, hm);
    final_reduce_kernel<<<1, 32>>>(out);
}

// round 2
// speedup vs baseline: 1.0097x; 1.0097x over previous
#include <cuda_runtime.h>
#include <math.h>

// Problem: B=64, V=8, J=17, H=256
// keypoints_gt: (B,V,J,2) float32   -> d_in[0], 17408 elems
// heatmap:      (B,V,1,H,H) float32 -> d_in[1], 33554432 elems
// out: scalar float = mean over B*V*J of -log(hm[b,v, clip(ceil(ky)), clip(ceil(kx))])

#define NTOT   8704      // 64*8*17
#define JDIM   17
#define HDIM   256
#define NBLK   68        // 68 * 128 = 8704 exactly
#define NTHR   128

__device__ float        g_partials[NBLK];
__device__ unsigned int g_count = 0;   // reset by the last block each call

__global__ __launch_bounds__(NTHR) void heatmap_ce_fused_kernel(
    const float* __restrict__ kp,   // (NTOT, 2)
    const float* __restrict__ hm,   // (B*V, H, H)
    float* __restrict__ out)
{
    const int i = blockIdx.x * NTHR + threadIdx.x;   // 0..8703, exact

    // coalesced float2 keypoint load
    const float2 k = reinterpret_cast<const float2*>(kp)[i];

    int xi = (int)ceilf(k.x);
    int yi = (int)ceilf(k.y);
    xi = min(max(xi, 0), HDIM - 1);
    yi = min(max(yi, 0), HDIM - 1);

    const int bv = i / JDIM;                         // (b*V + v)
    const long long off = (long long)bv * (HDIM * HDIM) + yi * HDIM + xi;

    const float val = __ldg(&hm[off]);
    float s = -__logf(val);   // vals in [0.001, 1]; fast log well within 1e-3 tol

    // warp reduce
    #pragma unroll
    for (int o = 16; o > 0; o >>= 1)
        s += __shfl_down_sync(0xFFFFFFFFu, s, o);

    __shared__ float sm[NTHR / 32];
    const int lane = threadIdx.x & 31;
    const int wid  = threadIdx.x >> 5;
    if (lane == 0) sm[wid] = s;
    __syncthreads();

    __shared__ bool is_last;
    if (threadIdx.x == 0) {
        float bs = sm[0] + sm[1] + sm[2] + sm[3];
        g_partials[blockIdx.x] = bs;
        __threadfence();                         // partial visible before count bump
        unsigned int prev = atomicAdd(&g_count, 1u);
        is_last = (prev == NBLK - 1);
    }
    __syncthreads();

    if (is_last && wid == 0) {
        // one warp sums the 68 partials in a fixed, deterministic order
        float s2 = 0.0f;
        #pragma unroll
        for (int b = lane; b < NBLK; b += 32)
            s2 += g_partials[b];
        #pragma unroll
        for (int o = 16; o > 0; o >>= 1)
            s2 += __shfl_down_sync(0xFFFFFFFFu, s2, o);
        if (lane == 0) {
            out[0] = s2 * (1.0f / (float)NTOT);
            g_count = 0;                         // rearm for next graph replay
        }
    }
}

extern "C" void kernel_launch(void* const* d_in, const int* in_sizes, int n_in,
                              void* d_out, int out_size)
{
    const float* kp = (const float*)d_in[0];
    const float* hm = (const float*)d_in[1];
    float* out = (float*)d_out;

    heatmap_ce_fused_kernel<<<NBLK, NTHR>>>(kp, hm, out);
}